// round 1
// baseline (speedup 1.0000x reference)
#include <cuda_runtime.h>

// out[b,c] = H @ x[b,c] @ H^T  for 65536 independent 32x32 fp32 matrices.
// One warp per matrix. 8x4 register tile per thread (32 FMAs / 12 smem floats
// per k-step -> FFMA-bound, not LDS-bound). T is stored back transposed into
// the same padded smem buffer so both stages share the conflict-free
// "broadcast row k" access pattern.

#define S_DIM 32
#define STRIDE 36              // 32 + 4 pad floats, keeps 16B alignment, breaks bank conflicts
#define MATS_PER_BLOCK 8
#define NTHREADS 256

__global__ __launch_bounds__(NTHREADS, 1)
void dct2d_kernel(const float* __restrict__ x,
                  const float* __restrict__ H,
                  float* __restrict__ out,
                  int nMat)
{
    __shared__ float Ht[S_DIM * S_DIM];                       // Ht[k][i] = H[i][k]
    __shared__ float buf[MATS_PER_BLOCK][S_DIM * STRIDE];     // X, then T^T (per warp)

    const int tid = threadIdx.x;

    // Build H^T once per block (H is tiny; L2-resident across the grid).
    #pragma unroll
    for (int q = 0; q < 4; q++) {
        int e = tid + NTHREADS * q;      // 0..1023
        int i = e >> 5;
        int k = e & 31;
        Ht[k * S_DIM + i] = H[e];
    }
    __syncthreads();

    const int warp = tid >> 5;
    const int lane = tid & 31;
    const int m = blockIdx.x * MATS_PER_BLOCK + warp;
    if (m >= nMat) return;

    float* Xs = buf[warp];
    const float4* __restrict__ src =
        reinterpret_cast<const float4*>(x + (size_t)m * (S_DIM * S_DIM));

    // ---- load X[32][32] into padded smem (coalesced float4) ----
    #pragma unroll
    for (int q = 0; q < 8; q++) {
        int f   = lane + 32 * q;   // float4 index 0..255
        int row = f >> 3;          // 8 float4 per row
        int c4  = f & 7;
        float4 v = src[f];
        *reinterpret_cast<float4*>(&Xs[row * STRIDE + c4 * 4]) = v;
    }
    __syncwarp();

    const int ti = lane >> 3;   // 0..3 -> rows ti*8 .. ti*8+7
    const int tj = lane & 7;    // 0..7 -> cols tj*4 .. tj*4+3

    float acc[8][4];
    #pragma unroll
    for (int r = 0; r < 8; r++)
        #pragma unroll
        for (int c = 0; c < 4; c++) acc[r][c] = 0.0f;

    // ---- stage 1: T[i][j] = sum_k Ht[k][i] * X[k][j] ----
    #pragma unroll 4
    for (int k = 0; k < S_DIM; k++) {
        float4 a0 = *reinterpret_cast<const float4*>(&Ht[k * S_DIM + ti * 8]);
        float4 a1 = *reinterpret_cast<const float4*>(&Ht[k * S_DIM + ti * 8 + 4]);
        float4 b4 = *reinterpret_cast<const float4*>(&Xs[k * STRIDE + tj * 4]);
        float a[8] = {a0.x, a0.y, a0.z, a0.w, a1.x, a1.y, a1.z, a1.w};
        float b[4] = {b4.x, b4.y, b4.z, b4.w};
        #pragma unroll
        for (int r = 0; r < 8; r++)
            #pragma unroll
            for (int c = 0; c < 4; c++)
                acc[r][c] = fmaf(a[r], b[c], acc[r][c]);
    }
    __syncwarp();

    // ---- write T transposed back into the same buffer: Tt[j][i] = T[i][j] ----
    #pragma unroll
    for (int c = 0; c < 4; c++) {
        float4 v0 = make_float4(acc[0][c], acc[1][c], acc[2][c], acc[3][c]);
        float4 v1 = make_float4(acc[4][c], acc[5][c], acc[6][c], acc[7][c]);
        int row = tj * 4 + c;
        *reinterpret_cast<float4*>(&Xs[row * STRIDE + ti * 8])     = v0;
        *reinterpret_cast<float4*>(&Xs[row * STRIDE + ti * 8 + 4]) = v1;
    }
    __syncwarp();

    #pragma unroll
    for (int r = 0; r < 8; r++)
        #pragma unroll
        for (int c = 0; c < 4; c++) acc[r][c] = 0.0f;

    // ---- stage 2: Out[i][l] = sum_k Tt[k][i] * Ht[k][l] ----
    #pragma unroll 4
    for (int k = 0; k < S_DIM; k++) {
        float4 a0 = *reinterpret_cast<const float4*>(&Xs[k * STRIDE + ti * 8]);
        float4 a1 = *reinterpret_cast<const float4*>(&Xs[k * STRIDE + ti * 8 + 4]);
        float4 b4 = *reinterpret_cast<const float4*>(&Ht[k * S_DIM + tj * 4]);
        float a[8] = {a0.x, a0.y, a0.z, a0.w, a1.x, a1.y, a1.z, a1.w};
        float b[4] = {b4.x, b4.y, b4.z, b4.w};
        #pragma unroll
        for (int r = 0; r < 8; r++)
            #pragma unroll
            for (int c = 0; c < 4; c++)
                acc[r][c] = fmaf(a[r], b[c], acc[r][c]);
    }

    // ---- store Out[32][32] (coalesced float4) ----
    float* __restrict__ dst = out + (size_t)m * (S_DIM * S_DIM);
    #pragma unroll
    for (int r = 0; r < 8; r++) {
        int i = ti * 8 + r;
        *reinterpret_cast<float4*>(&dst[i * S_DIM + tj * 4]) =
            make_float4(acc[r][0], acc[r][1], acc[r][2], acc[r][3]);
    }
}

extern "C" void kernel_launch(void* const* d_in, const int* in_sizes, int n_in,
                              void* d_out, int out_size)
{
    const float* x = (const float*)d_in[0];   // [B, C, 32, 32] fp32
    const float* H = (const float*)d_in[1];   // [32, 32] fp32
    float* out = (float*)d_out;

    int nMat = in_sizes[0] / (S_DIM * S_DIM); // B*C = 65536
    int blocks = (nMat + MATS_PER_BLOCK - 1) / MATS_PER_BLOCK;

    dct2d_kernel<<<blocks, NTHREADS>>>(x, H, out, nMat);
}

// round 2
// speedup vs baseline: 1.0030x; 1.0030x over previous
#include <cuda_runtime.h>

// out[b,c] = H @ x[b,c] @ H^T  for 65536 independent 32x32 fp32 matrices.
// One warp per matrix. 8x4 register tile per thread (32 FMAs / 12 smem floats
// per k-step -> FFMA-bound, not LDS-bound). T is stored back transposed into
// the same padded smem buffer so both stages share the conflict-free
// "broadcast row k" access pattern.

#define S_DIM 32
#define STRIDE 36              // 32 + 4 pad floats, keeps 16B alignment, breaks bank conflicts
#define MATS_PER_BLOCK 8
#define NTHREADS 256

__global__ __launch_bounds__(NTHREADS, 1)
void dct2d_kernel(const float* __restrict__ x,
                  const float* __restrict__ H,
                  float* __restrict__ out,
                  int nMat)
{
    __shared__ float Ht[S_DIM * S_DIM];                       // Ht[k][i] = H[i][k]
    __shared__ float buf[MATS_PER_BLOCK][S_DIM * STRIDE];     // X, then T^T (per warp)

    const int tid = threadIdx.x;

    // Build H^T once per block (H is tiny; L2-resident across the grid).
    #pragma unroll
    for (int q = 0; q < 4; q++) {
        int e = tid + NTHREADS * q;      // 0..1023
        int i = e >> 5;
        int k = e & 31;
        Ht[k * S_DIM + i] = H[e];
    }
    __syncthreads();

    const int warp = tid >> 5;
    const int lane = tid & 31;
    const int m = blockIdx.x * MATS_PER_BLOCK + warp;
    if (m >= nMat) return;

    float* Xs = buf[warp];
    const float4* __restrict__ src =
        reinterpret_cast<const float4*>(x + (size_t)m * (S_DIM * S_DIM));

    // ---- load X[32][32] into padded smem (coalesced float4) ----
    #pragma unroll
    for (int q = 0; q < 8; q++) {
        int f   = lane + 32 * q;   // float4 index 0..255
        int row = f >> 3;          // 8 float4 per row
        int c4  = f & 7;
        float4 v = src[f];
        *reinterpret_cast<float4*>(&Xs[row * STRIDE + c4 * 4]) = v;
    }
    __syncwarp();

    const int ti = lane >> 3;   // 0..3 -> rows ti*8 .. ti*8+7
    const int tj = lane & 7;    // 0..7 -> cols tj*4 .. tj*4+3

    float acc[8][4];
    #pragma unroll
    for (int r = 0; r < 8; r++)
        #pragma unroll
        for (int c = 0; c < 4; c++) acc[r][c] = 0.0f;

    // ---- stage 1: T[i][j] = sum_k Ht[k][i] * X[k][j] ----
    #pragma unroll 4
    for (int k = 0; k < S_DIM; k++) {
        float4 a0 = *reinterpret_cast<const float4*>(&Ht[k * S_DIM + ti * 8]);
        float4 a1 = *reinterpret_cast<const float4*>(&Ht[k * S_DIM + ti * 8 + 4]);
        float4 b4 = *reinterpret_cast<const float4*>(&Xs[k * STRIDE + tj * 4]);
        float a[8] = {a0.x, a0.y, a0.z, a0.w, a1.x, a1.y, a1.z, a1.w};
        float b[4] = {b4.x, b4.y, b4.z, b4.w};
        #pragma unroll
        for (int r = 0; r < 8; r++)
            #pragma unroll
            for (int c = 0; c < 4; c++)
                acc[r][c] = fmaf(a[r], b[c], acc[r][c]);
    }
    __syncwarp();

    // ---- write T transposed back into the same buffer: Tt[j][i] = T[i][j] ----
    #pragma unroll
    for (int c = 0; c < 4; c++) {
        float4 v0 = make_float4(acc[0][c], acc[1][c], acc[2][c], acc[3][c]);
        float4 v1 = make_float4(acc[4][c], acc[5][c], acc[6][c], acc[7][c]);
        int row = tj * 4 + c;
        *reinterpret_cast<float4*>(&Xs[row * STRIDE + ti * 8])     = v0;
        *reinterpret_cast<float4*>(&Xs[row * STRIDE + ti * 8 + 4]) = v1;
    }
    __syncwarp();

    #pragma unroll
    for (int r = 0; r < 8; r++)
        #pragma unroll
        for (int c = 0; c < 4; c++) acc[r][c] = 0.0f;

    // ---- stage 2: Out[i][l] = sum_k Tt[k][i] * Ht[k][l] ----
    #pragma unroll 4
    for (int k = 0; k < S_DIM; k++) {
        float4 a0 = *reinterpret_cast<const float4*>(&Xs[k * STRIDE + ti * 8]);
        float4 a1 = *reinterpret_cast<const float4*>(&Xs[k * STRIDE + ti * 8 + 4]);
        float4 b4 = *reinterpret_cast<const float4*>(&Ht[k * S_DIM + tj * 4]);
        float a[8] = {a0.x, a0.y, a0.z, a0.w, a1.x, a1.y, a1.z, a1.w};
        float b[4] = {b4.x, b4.y, b4.z, b4.w};
        #pragma unroll
        for (int r = 0; r < 8; r++)
            #pragma unroll
            for (int c = 0; c < 4; c++)
                acc[r][c] = fmaf(a[r], b[c], acc[r][c]);
    }

    // ---- store Out[32][32] (coalesced float4) ----
    float* __restrict__ dst = out + (size_t)m * (S_DIM * S_DIM);
    #pragma unroll
    for (int r = 0; r < 8; r++) {
        int i = ti * 8 + r;
        *reinterpret_cast<float4*>(&dst[i * S_DIM + tj * 4]) =
            make_float4(acc[r][0], acc[r][1], acc[r][2], acc[r][3]);
    }
}

extern "C" void kernel_launch(void* const* d_in, const int* in_sizes, int n_in,
                              void* d_out, int out_size)
{
    const float* x = (const float*)d_in[0];   // [B, C, 32, 32] fp32
    const float* H = (const float*)d_in[1];   // [32, 32] fp32
    float* out = (float*)d_out;

    int nMat = in_sizes[0] / (S_DIM * S_DIM); // B*C = 65536
    int blocks = (nMat + MATS_PER_BLOCK - 1) / MATS_PER_BLOCK;

    dct2d_kernel<<<blocks, NTHREADS>>>(x, H, out, nMat);
}

// round 3
// speedup vs baseline: 1.1676x; 1.1642x over previous
#include <cuda_runtime.h>

// out[b,c] = H @ x[b,c] @ H^T for 65536 independent 32x32 fp32 matrices.
// One warp per 2 matrices. 8x4 register tile per thread per matrix, with
// accumulators packed as f32x2 row-pairs -> fma.rn.f32x2 does 2 FMAs/instr
// (2x the scalar FFMA issue rate on sm_103a). Ht loads and B-splats are
// shared across the 2 matrices to keep LDS traffic under the new FMA floor.

#define S_DIM 32
#define STRIDE 36              // 32 + 4 pad floats: 16B-aligned rows, conflict-free k-broadcasts
#define WARPS_PER_BLOCK 4
#define MATS_PER_WARP 2
#define MATS_PER_BLOCK (WARPS_PER_BLOCK * MATS_PER_WARP)
#define NTHREADS (WARPS_PER_BLOCK * 32)

typedef unsigned long long u64;

__device__ __forceinline__ void fma2(u64& d, u64 a, u64 b) {
    asm("fma.rn.f32x2 %0, %1, %2, %0;" : "+l"(d) : "l"(a), "l"(b));
}
__device__ __forceinline__ u64 splat2(float v) {
    u64 r;
    asm("mov.b64 %0, {%1, %1};" : "=l"(r) : "f"(v));
    return r;
}
__device__ __forceinline__ float2 unpack2(u64 u) {
    float2 f;
    asm("mov.b64 {%0, %1}, %2;" : "=f"(f.x), "=f"(f.y) : "l"(u));
    return f;
}

__global__ __launch_bounds__(NTHREADS, 4)
void dct2d_kernel(const float* __restrict__ x,
                  const float* __restrict__ H,
                  float* __restrict__ out,
                  int nMat)
{
    __shared__ __align__(16) float Ht[S_DIM * S_DIM];                    // Ht[k][i] = H[i][k]
    __shared__ __align__(16) float buf[MATS_PER_BLOCK][S_DIM * STRIDE];  // X, then T^T

    const int tid = threadIdx.x;

    // Build H^T once per block.
    #pragma unroll
    for (int e = tid; e < S_DIM * S_DIM; e += NTHREADS) {
        int i = e >> 5;
        int k = e & 31;
        Ht[k * S_DIM + i] = H[e];
    }
    __syncthreads();

    const int warp = tid >> 5;
    const int lane = tid & 31;
    const int m0 = (blockIdx.x * WARPS_PER_BLOCK + warp) * MATS_PER_WARP;
    if (m0 >= nMat) return;

    float* Xs0 = buf[warp * MATS_PER_WARP + 0];
    float* Xs1 = buf[warp * MATS_PER_WARP + 1];

    const float4* __restrict__ src0 =
        reinterpret_cast<const float4*>(x + (size_t)m0 * (S_DIM * S_DIM));
    const float4* __restrict__ src1 =
        reinterpret_cast<const float4*>(x + (size_t)(m0 + 1) * (S_DIM * S_DIM));

    // ---- load both X[32][32] into padded smem (coalesced float4) ----
    #pragma unroll
    for (int q = 0; q < 8; q++) {
        int f   = lane + 32 * q;
        int row = f >> 3;
        int c4  = f & 7;
        *reinterpret_cast<float4*>(&Xs0[row * STRIDE + c4 * 4]) = src0[f];
        *reinterpret_cast<float4*>(&Xs1[row * STRIDE + c4 * 4]) = src1[f];
    }
    __syncwarp();

    const int ti = lane >> 3;   // rows ti*8 .. ti*8+7
    const int tj = lane & 7;    // cols tj*4 .. tj*4+3

    // acc[p][c] packs rows (ti*8+2p, ti*8+2p+1) at column tj*4+c
    u64 acc0[4][4], acc1[4][4];
    #pragma unroll
    for (int p = 0; p < 4; p++)
        #pragma unroll
        for (int c = 0; c < 4; c++) { acc0[p][c] = 0ull; acc1[p][c] = 0ull; }

    // ---- stage 1: T[i][j] = sum_k Ht[k][i] * X[k][j] ----
    // a-pairs come free from the 16B Ht loads; b needs splats (per matrix).
    #pragma unroll 8
    for (int k = 0; k < S_DIM; k++) {
        const ulonglong2* ap =
            reinterpret_cast<const ulonglong2*>(&Ht[k * S_DIM + ti * 8]);
        ulonglong2 aA = ap[0], aB = ap[1];
        u64 a[4] = {aA.x, aA.y, aB.x, aB.y};

        float4 b0 = *reinterpret_cast<const float4*>(&Xs0[k * STRIDE + tj * 4]);
        float4 b1 = *reinterpret_cast<const float4*>(&Xs1[k * STRIDE + tj * 4]);
        u64 bb0[4] = {splat2(b0.x), splat2(b0.y), splat2(b0.z), splat2(b0.w)};
        u64 bb1[4] = {splat2(b1.x), splat2(b1.y), splat2(b1.z), splat2(b1.w)};

        #pragma unroll
        for (int p = 0; p < 4; p++)
            #pragma unroll
            for (int c = 0; c < 4; c++) {
                fma2(acc0[p][c], a[p], bb0[c]);
                fma2(acc1[p][c], a[p], bb1[c]);
            }
    }
    __syncwarp();

    // ---- write T transposed back: Tt[j][i] = T[i][j] ----
    #pragma unroll
    for (int c = 0; c < 4; c++) {
        int row = tj * 4 + c;
        float2 f0 = unpack2(acc0[0][c]), f1 = unpack2(acc0[1][c]);
        float2 f2 = unpack2(acc0[2][c]), f3 = unpack2(acc0[3][c]);
        *reinterpret_cast<float4*>(&Xs0[row * STRIDE + ti * 8]) =
            make_float4(f0.x, f0.y, f1.x, f1.y);
        *reinterpret_cast<float4*>(&Xs0[row * STRIDE + ti * 8 + 4]) =
            make_float4(f2.x, f2.y, f3.x, f3.y);
        f0 = unpack2(acc1[0][c]); f1 = unpack2(acc1[1][c]);
        f2 = unpack2(acc1[2][c]); f3 = unpack2(acc1[3][c]);
        *reinterpret_cast<float4*>(&Xs1[row * STRIDE + ti * 8]) =
            make_float4(f0.x, f0.y, f1.x, f1.y);
        *reinterpret_cast<float4*>(&Xs1[row * STRIDE + ti * 8 + 4]) =
            make_float4(f2.x, f2.y, f3.x, f3.y);
    }
    __syncwarp();

    #pragma unroll
    for (int p = 0; p < 4; p++)
        #pragma unroll
        for (int c = 0; c < 4; c++) { acc0[p][c] = 0ull; acc1[p][c] = 0ull; }

    // ---- stage 2: Out[i][l] = sum_k Tt[k][i] * Ht[k][l] ----
    // a-pairs per matrix from Tt; b (Ht) splats SHARED across both matrices.
    #pragma unroll 8
    for (int k = 0; k < S_DIM; k++) {
        const ulonglong2* a0p =
            reinterpret_cast<const ulonglong2*>(&Xs0[k * STRIDE + ti * 8]);
        const ulonglong2* a1p =
            reinterpret_cast<const ulonglong2*>(&Xs1[k * STRIDE + ti * 8]);
        ulonglong2 a0A = a0p[0], a0B = a0p[1];
        ulonglong2 a1A = a1p[0], a1B = a1p[1];
        u64 a0[4] = {a0A.x, a0A.y, a0B.x, a0B.y};
        u64 a1[4] = {a1A.x, a1A.y, a1B.x, a1B.y};

        float4 b4 = *reinterpret_cast<const float4*>(&Ht[k * S_DIM + tj * 4]);
        u64 bb[4] = {splat2(b4.x), splat2(b4.y), splat2(b4.z), splat2(b4.w)};

        #pragma unroll
        for (int p = 0; p < 4; p++)
            #pragma unroll
            for (int c = 0; c < 4; c++) {
                fma2(acc0[p][c], a0[p], bb[c]);
                fma2(acc1[p][c], a1[p], bb[c]);
            }
    }

    // ---- store Out[32][32] for both matrices (coalesced float4) ----
    float* __restrict__ dst0 = out + (size_t)m0 * (S_DIM * S_DIM);
    float* __restrict__ dst1 = out + (size_t)(m0 + 1) * (S_DIM * S_DIM);
    #pragma unroll
    for (int p = 0; p < 4; p++) {
        int i0 = ti * 8 + 2 * p;
        float2 c0 = unpack2(acc0[p][0]), c1 = unpack2(acc0[p][1]);
        float2 c2 = unpack2(acc0[p][2]), c3 = unpack2(acc0[p][3]);
        *reinterpret_cast<float4*>(&dst0[i0 * S_DIM + tj * 4]) =
            make_float4(c0.x, c1.x, c2.x, c3.x);
        *reinterpret_cast<float4*>(&dst0[(i0 + 1) * S_DIM + tj * 4]) =
            make_float4(c0.y, c1.y, c2.y, c3.y);
        c0 = unpack2(acc1[p][0]); c1 = unpack2(acc1[p][1]);
        c2 = unpack2(acc1[p][2]); c3 = unpack2(acc1[p][3]);
        *reinterpret_cast<float4*>(&dst1[i0 * S_DIM + tj * 4]) =
            make_float4(c0.x, c1.x, c2.x, c3.x);
        *reinterpret_cast<float4*>(&dst1[(i0 + 1) * S_DIM + tj * 4]) =
            make_float4(c0.y, c1.y, c2.y, c3.y);
    }
}

extern "C" void kernel_launch(void* const* d_in, const int* in_sizes, int n_in,
                              void* d_out, int out_size)
{
    const float* x = (const float*)d_in[0];   // [B, C, 32, 32] fp32
    const float* H = (const float*)d_in[1];   // [32, 32] fp32
    float* out = (float*)d_out;

    int nMat = in_sizes[0] / (S_DIM * S_DIM); // 65536
    int blocks = (nMat + MATS_PER_BLOCK - 1) / MATS_PER_BLOCK;

    dct2d_kernel<<<blocks, NTHREADS>>>(x, H, out, nMat);
}